// round 7
// baseline (speedup 1.0000x reference)
#include <cuda_runtime.h>
#include <cstdint>

#define TT 2048
#define DD 2048
#define EE 8
#define HH 1408
#define HSD 2816

// GEMM tiling (same as R1)
#define BM 64
#define BN 64
#define BK 32

// packed f32x2 FMA: c.lo += a.lo*b.lo ; c.hi += a.hi*b.hi
#define FMA2(c, a, b) asm("fma.rn.f32x2 %0, %1, %2, %0;" : "+l"(c) : "l"(a), "l"(b))

__device__ __forceinline__ float2 up2(unsigned long long v) {
    float2 r; asm("mov.b64 {%0,%1}, %2;" : "=f"(r.x), "=f"(r.y) : "l"(v)); return r;
}

// ---------------- scratch (device globals; no runtime allocation) ------------
__device__ int   g_cnt[EE];
__device__ int   g_perm[EE * TT];
__device__ float g_cw[EE * TT];
__device__ float g_sgate[TT];
__device__ float g_h[(size_t)EE * TT * HH];
__device__ float g_hs[(size_t)TT * HSD];

// ---------------- kernel 0: reset router counters -----------------------------
__global__ void zero_cnt_kernel() {
    if (threadIdx.x < EE) g_cnt[threadIdx.x] = 0;
}

// ---------------- kernel 1: router (unchanged from R1) -------------------------
__global__ void __launch_bounds__(256) router_kernel(
    const float* __restrict__ x,
    const float* __restrict__ gate_w,
    const float* __restrict__ shgate_w)
{
    int t = blockIdx.x;
    const float* xr = x + (size_t)t * DD;
    float acc[9];
#pragma unroll
    for (int v = 0; v < 9; v++) acc[v] = 0.f;
    for (int j = threadIdx.x; j < DD; j += 256) {
        float xv = xr[j];
#pragma unroll
        for (int e = 0; e < EE; e++) acc[e] = fmaf(xv, gate_w[e * DD + j], acc[e]);
        acc[8] = fmaf(xv, shgate_w[j], acc[8]);
    }
#pragma unroll
    for (int o = 16; o > 0; o >>= 1) {
#pragma unroll
        for (int v = 0; v < 9; v++) acc[v] += __shfl_down_sync(0xffffffffu, acc[v], o);
    }
    __shared__ float sred[9][8];
    int lane = threadIdx.x & 31, wid = threadIdx.x >> 5;
    if (lane == 0) {
#pragma unroll
        for (int v = 0; v < 9; v++) sred[v][wid] = acc[v];
    }
    __syncthreads();
    if (threadIdx.x == 0) {
        float l[9];
#pragma unroll
        for (int v = 0; v < 9; v++) {
            float s = 0.f;
#pragma unroll
            for (int w = 0; w < 8; w++) s += sred[v][w];
            l[v] = s;
        }
        float m = l[0];
#pragma unroll
        for (int e = 1; e < EE; e++) m = fmaxf(m, l[e]);
        float p[EE];
#pragma unroll
        for (int e = 0; e < EE; e++) p[e] = expf(l[e] - m);
        int i0 = 0;
#pragma unroll
        for (int e = 1; e < EE; e++) if (p[e] > p[i0]) i0 = e;
        int i1 = (i0 == 0) ? 1 : 0;
#pragma unroll
        for (int e = 0; e < EE; e++) if (e != i0 && p[e] > p[i1]) i1 = e;
        float inv = 1.f / (p[i0] + p[i1]);
        int q0 = atomicAdd(&g_cnt[i0], 1);
        g_perm[i0 * TT + q0] = t;
        g_cw[i0 * TT + q0]   = p[i0] * inv;
        int q1 = atomicAdd(&g_cnt[i1], 1);
        g_perm[i1 * TT + q1] = t;
        g_cw[i1 * TT + q1]   = p[i1] * inv;
        g_sgate[t] = 1.f / (1.f + expf(-l[8]));
    }
}

// ---------------- kernel 2: expert gate/up GEMM (packed f32x2) -----------------
__global__ void __launch_bounds__(256) expert_gateup_kernel(
    const float* __restrict__ x,
    const float* __restrict__ w_gate,
    const float* __restrict__ w_up)
{
    int e = blockIdx.z;
    int n = g_cnt[e];
    int row0 = blockIdx.y * BM;
    if (row0 >= n) return;
    int col0 = blockIdx.x * BN;

    __shared__ alignas(16) float As2[BM][68];   // k-duplicated pairs: col 2k,2k+1
    __shared__ alignas(16) float Bg[BK][68];
    __shared__ alignas(16) float Bu[BK][68];

    int tid = threadIdx.x;
    int tx = tid & 15, ty = tid >> 4;
    const float* wg = w_gate + (size_t)e * DD * HH;
    const float* wu = w_up   + (size_t)e * DD * HH;

    int tok[2];
#pragma unroll
    for (int i = 0; i < 2; i++) {
        int idx = tid + i * 256;
        int r = idx >> 3;
        int pos = row0 + r;
        tok[i] = (pos < n) ? g_perm[e * TT + pos] : g_perm[e * TT];
    }

    unsigned long long ag[4][2], au[4][2];
#pragma unroll
    for (int a = 0; a < 4; a++)
#pragma unroll
        for (int b = 0; b < 2; b++) { ag[a][b] = 0ull; au[a][b] = 0ull; }

    for (int k0 = 0; k0 < DD; k0 += BK) {
#pragma unroll
        for (int i = 0; i < 2; i++) {
            int idx = tid + i * 256;
            int r = idx >> 3;
            int kc = (idx & 7) << 2;
            float4 v = *(const float4*)(x + (size_t)tok[i] * DD + k0 + kc);
            *(float4*)&As2[r][2 * kc]     = make_float4(v.x, v.x, v.y, v.y);
            *(float4*)&As2[r][2 * kc + 4] = make_float4(v.z, v.z, v.w, v.w);
        }
#pragma unroll
        for (int i = 0; i < 2; i++) {
            int idx = tid + i * 256;
            int kk = idx >> 4;
            int c = (idx & 15) << 2;
            size_t off = (size_t)(k0 + kk) * HH + col0 + c;
            *(float4*)&Bg[kk][c] = *(const float4*)(wg + off);
            *(float4*)&Bu[kk][c] = *(const float4*)(wu + off);
        }
        __syncthreads();
#pragma unroll
        for (int kk = 0; kk < BK; kk++) {
            unsigned long long ap[4];
#pragma unroll
            for (int tm = 0; tm < 4; tm++)
                ap[tm] = *(const unsigned long long*)&As2[ty * 4 + tm][2 * kk];
            ulonglong2 bgv = *(const ulonglong2*)&Bg[kk][tx * 4];
            ulonglong2 buv = *(const ulonglong2*)&Bu[kk][tx * 4];
#pragma unroll
            for (int tm = 0; tm < 4; tm++) {
                FMA2(ag[tm][0], ap[tm], bgv.x);
                FMA2(ag[tm][1], ap[tm], bgv.y);
                FMA2(au[tm][0], ap[tm], buv.x);
                FMA2(au[tm][1], ap[tm], buv.y);
            }
        }
        __syncthreads();
    }
#pragma unroll
    for (int tm = 0; tm < 4; tm++) {
        int pos = row0 + ty * 4 + tm;
        if (pos < n) {
            float* o = g_h + ((size_t)e * TT + pos) * HH + col0 + tx * 4;
            float2 g01 = up2(ag[tm][0]), g23 = up2(ag[tm][1]);
            float2 u01 = up2(au[tm][0]), u23 = up2(au[tm][1]);
            o[0] = u01.x * (g01.x / (1.f + expf(-g01.x)));
            o[1] = u01.y * (g01.y / (1.f + expf(-g01.y)));
            o[2] = u23.x * (g23.x / (1.f + expf(-g23.x)));
            o[3] = u23.y * (g23.y / (1.f + expf(-g23.y)));
        }
    }
}

// ---------------- kernel 3: shared gate/up GEMM (packed f32x2) ------------------
__global__ void __launch_bounds__(256) shared_gateup_kernel(
    const float* __restrict__ x,
    const float* __restrict__ shw_gate,
    const float* __restrict__ shw_up)
{
    int row0 = blockIdx.y * BM;
    int col0 = blockIdx.x * BN;

    __shared__ alignas(16) float As2[BM][68];
    __shared__ alignas(16) float Bg[BK][68];
    __shared__ alignas(16) float Bu[BK][68];

    int tid = threadIdx.x;
    int tx = tid & 15, ty = tid >> 4;

    unsigned long long ag[4][2], au[4][2];
#pragma unroll
    for (int a = 0; a < 4; a++)
#pragma unroll
        for (int b = 0; b < 2; b++) { ag[a][b] = 0ull; au[a][b] = 0ull; }

    for (int k0 = 0; k0 < DD; k0 += BK) {
#pragma unroll
        for (int i = 0; i < 2; i++) {
            int idx = tid + i * 256;
            int r = idx >> 3;
            int kc = (idx & 7) << 2;
            float4 v = *(const float4*)(x + (size_t)(row0 + r) * DD + k0 + kc);
            *(float4*)&As2[r][2 * kc]     = make_float4(v.x, v.x, v.y, v.y);
            *(float4*)&As2[r][2 * kc + 4] = make_float4(v.z, v.z, v.w, v.w);
        }
#pragma unroll
        for (int i = 0; i < 2; i++) {
            int idx = tid + i * 256;
            int kk = idx >> 4;
            int c = (idx & 15) << 2;
            size_t off = (size_t)(k0 + kk) * HSD + col0 + c;
            *(float4*)&Bg[kk][c] = *(const float4*)(shw_gate + off);
            *(float4*)&Bu[kk][c] = *(const float4*)(shw_up + off);
        }
        __syncthreads();
#pragma unroll
        for (int kk = 0; kk < BK; kk++) {
            unsigned long long ap[4];
#pragma unroll
            for (int tm = 0; tm < 4; tm++)
                ap[tm] = *(const unsigned long long*)&As2[ty * 4 + tm][2 * kk];
            ulonglong2 bgv = *(const ulonglong2*)&Bg[kk][tx * 4];
            ulonglong2 buv = *(const ulonglong2*)&Bu[kk][tx * 4];
#pragma unroll
            for (int tm = 0; tm < 4; tm++) {
                FMA2(ag[tm][0], ap[tm], bgv.x);
                FMA2(ag[tm][1], ap[tm], bgv.y);
                FMA2(au[tm][0], ap[tm], buv.x);
                FMA2(au[tm][1], ap[tm], buv.y);
            }
        }
        __syncthreads();
    }
#pragma unroll
    for (int tm = 0; tm < 4; tm++) {
        int trow = row0 + ty * 4 + tm;
        float* o = g_hs + (size_t)trow * HSD + col0 + tx * 4;
        float2 g01 = up2(ag[tm][0]), g23 = up2(ag[tm][1]);
        float2 u01 = up2(au[tm][0]), u23 = up2(au[tm][1]);
        o[0] = u01.x * (g01.x / (1.f + expf(-g01.x)));
        o[1] = u01.y * (g01.y / (1.f + expf(-g01.y)));
        o[2] = u23.x * (g23.x / (1.f + expf(-g23.x)));
        o[3] = u23.y * (g23.y / (1.f + expf(-g23.y)));
    }
}

// ---------------- kernel 4: shared down-proj (packed f32x2) ---------------------
__global__ void __launch_bounds__(256) shared_down_kernel(
    const float* __restrict__ shw_down,
    float* __restrict__ out)
{
    int row0 = blockIdx.y * BM;
    int col0 = blockIdx.x * BN;

    __shared__ alignas(16) float As2[BM][68];
    __shared__ alignas(16) float Bs[BK][68];

    int tid = threadIdx.x;
    int tx = tid & 15, ty = tid >> 4;

    unsigned long long acc[4][2];
#pragma unroll
    for (int a = 0; a < 4; a++)
#pragma unroll
        for (int b = 0; b < 2; b++) acc[a][b] = 0ull;

    for (int k0 = 0; k0 < HSD; k0 += BK) {
#pragma unroll
        for (int i = 0; i < 2; i++) {
            int idx = tid + i * 256;
            int r = idx >> 3;
            int kc = (idx & 7) << 2;
            float4 v = *(const float4*)(g_hs + (size_t)(row0 + r) * HSD + k0 + kc);
            *(float4*)&As2[r][2 * kc]     = make_float4(v.x, v.x, v.y, v.y);
            *(float4*)&As2[r][2 * kc + 4] = make_float4(v.z, v.z, v.w, v.w);
        }
#pragma unroll
        for (int i = 0; i < 2; i++) {
            int idx = tid + i * 256;
            int kk = idx >> 4;
            int c = (idx & 15) << 2;
            *(float4*)&Bs[kk][c] = *(const float4*)(shw_down + (size_t)(k0 + kk) * DD + col0 + c);
        }
        __syncthreads();
#pragma unroll
        for (int kk = 0; kk < BK; kk++) {
            unsigned long long ap[4];
#pragma unroll
            for (int tm = 0; tm < 4; tm++)
                ap[tm] = *(const unsigned long long*)&As2[ty * 4 + tm][2 * kk];
            ulonglong2 bv = *(const ulonglong2*)&Bs[kk][tx * 4];
#pragma unroll
            for (int tm = 0; tm < 4; tm++) {
                FMA2(acc[tm][0], ap[tm], bv.x);
                FMA2(acc[tm][1], ap[tm], bv.y);
            }
        }
        __syncthreads();
    }
#pragma unroll
    for (int tm = 0; tm < 4; tm++) {
        int trow = row0 + ty * 4 + tm;
        float sg = g_sgate[trow];
        float2 c01 = up2(acc[tm][0]), c23 = up2(acc[tm][1]);
        float4 v;
        v.x = sg * c01.x; v.y = sg * c01.y;
        v.z = sg * c23.x; v.w = sg * c23.y;
        *(float4*)(out + (size_t)trow * DD + col0 + tx * 4) = v;
    }
}

// ---------------- kernel 5: expert down-proj (packed f32x2, atomicAdd) ----------
__global__ void __launch_bounds__(256) expert_down_kernel(
    const float* __restrict__ w_down,
    float* __restrict__ out)
{
    int e = blockIdx.z;
    int n = g_cnt[e];
    int row0 = blockIdx.y * BM;
    if (row0 >= n) return;
    int col0 = blockIdx.x * BN;

    __shared__ alignas(16) float As2[BM][68];
    __shared__ alignas(16) float Bs[BK][68];

    int tid = threadIdx.x;
    int tx = tid & 15, ty = tid >> 4;
    const float* wd = w_down + (size_t)e * HH * DD;
    const float* Abase = g_h + ((size_t)e * TT + row0) * HH;

    unsigned long long acc[4][2];
#pragma unroll
    for (int a = 0; a < 4; a++)
#pragma unroll
        for (int b = 0; b < 2; b++) acc[a][b] = 0ull;

    for (int k0 = 0; k0 < HH; k0 += BK) {
#pragma unroll
        for (int i = 0; i < 2; i++) {
            int idx = tid + i * 256;
            int r = idx >> 3;
            int kc = (idx & 7) << 2;
            float4 v = *(const float4*)(Abase + (size_t)r * HH + k0 + kc);
            *(float4*)&As2[r][2 * kc]     = make_float4(v.x, v.x, v.y, v.y);
            *(float4*)&As2[r][2 * kc + 4] = make_float4(v.z, v.z, v.w, v.w);
        }
#pragma unroll
        for (int i = 0; i < 2; i++) {
            int idx = tid + i * 256;
            int kk = idx >> 4;
            int c = (idx & 15) << 2;
            *(float4*)&Bs[kk][c] = *(const float4*)(wd + (size_t)(k0 + kk) * DD + col0 + c);
        }
        __syncthreads();
#pragma unroll
        for (int kk = 0; kk < BK; kk++) {
            unsigned long long ap[4];
#pragma unroll
            for (int tm = 0; tm < 4; tm++)
                ap[tm] = *(const unsigned long long*)&As2[ty * 4 + tm][2 * kk];
            ulonglong2 bv = *(const ulonglong2*)&Bs[kk][tx * 4];
#pragma unroll
            for (int tm = 0; tm < 4; tm++) {
                FMA2(acc[tm][0], ap[tm], bv.x);
                FMA2(acc[tm][1], ap[tm], bv.y);
            }
        }
        __syncthreads();
    }
#pragma unroll
    for (int tm = 0; tm < 4; tm++) {
        int pos = row0 + ty * 4 + tm;
        if (pos < n) {
            int t = g_perm[e * TT + pos];
            float cw = g_cw[e * TT + pos];
            float* o = out + (size_t)t * DD + col0 + tx * 4;
            float2 c01 = up2(acc[tm][0]), c23 = up2(acc[tm][1]);
            atomicAdd(&o[0], cw * c01.x);
            atomicAdd(&o[1], cw * c01.y);
            atomicAdd(&o[2], cw * c23.x);
            atomicAdd(&o[3], cw * c23.y);
        }
    }
}

// ---------------- launch --------------------------------------------------------
extern "C" void kernel_launch(void* const* d_in, const int* in_sizes, int n_in,
                              void* d_out, int out_size)
{
    const float* x        = (const float*)d_in[0];
    const float* gate_w   = (const float*)d_in[1];
    const float* w_gate   = (const float*)d_in[2];
    const float* w_up     = (const float*)d_in[3];
    const float* w_down   = (const float*)d_in[4];
    const float* shgate_w = (const float*)d_in[5];
    const float* shw_gate = (const float*)d_in[6];
    const float* shw_up   = (const float*)d_in[7];
    const float* shw_down = (const float*)d_in[8];
    float* out = (float*)d_out;

    zero_cnt_kernel<<<1, 32>>>();
    router_kernel<<<TT, 256>>>(x, gate_w, shgate_w);
    expert_gateup_kernel<<<dim3(HH / BN, TT / BM, EE), 256>>>(x, w_gate, w_up);
    shared_gateup_kernel<<<dim3(HSD / BN, TT / BM), 256>>>(x, shw_gate, shw_up);
    shared_down_kernel<<<dim3(DD / BN, TT / BM), 256>>>(shw_down, out);
    expert_down_kernel<<<dim3(DD / BN, TT / BM, EE), 256>>>(w_down, out);
}

// round 11
// speedup vs baseline: 1.3198x; 1.3198x over previous
#include <cuda_runtime.h>
#include <cstdint>

#define TT 2048
#define DD 2048
#define EE 8
#define HH 1408
#define HSD 2816

#define BK 16
#define SSTR 132   // smem row stride (floats) for [BK][128] tiles

__device__ __forceinline__ float silu(float g) { return g / (1.f + __expf(-g)); }

// ---------------- scratch ------------------------------------------------------
__device__ int   g_cnt[EE];
__device__ int   g_perm[EE * TT];
__device__ float g_cw[EE * TT];
__device__ float g_sgate[TT];
__device__ float g_h[(size_t)EE * TT * HH];
__device__ float g_hs[(size_t)TT * HSD];

// ---------------- kernel 0 -------------------------------------------------------
__global__ void zero_cnt_kernel() {
    if (threadIdx.x < EE) g_cnt[threadIdx.x] = 0;
}

// ---------------- kernel 1: router -----------------------------------------------
__global__ void __launch_bounds__(256) router_kernel(
    const float* __restrict__ x,
    const float* __restrict__ gate_w,
    const float* __restrict__ shgate_w)
{
    int t = blockIdx.x;
    const float* xr = x + (size_t)t * DD;
    float acc[9];
#pragma unroll
    for (int v = 0; v < 9; v++) acc[v] = 0.f;
    for (int j = threadIdx.x; j < DD; j += 256) {
        float xv = xr[j];
#pragma unroll
        for (int e = 0; e < EE; e++) acc[e] = fmaf(xv, gate_w[e * DD + j], acc[e]);
        acc[8] = fmaf(xv, shgate_w[j], acc[8]);
    }
#pragma unroll
    for (int o = 16; o > 0; o >>= 1) {
#pragma unroll
        for (int v = 0; v < 9; v++) acc[v] += __shfl_down_sync(0xffffffffu, acc[v], o);
    }
    __shared__ float sred[9][8];
    int lane = threadIdx.x & 31, wid = threadIdx.x >> 5;
    if (lane == 0) {
#pragma unroll
        for (int v = 0; v < 9; v++) sred[v][wid] = acc[v];
    }
    __syncthreads();
    if (threadIdx.x == 0) {
        float l[9];
#pragma unroll
        for (int v = 0; v < 9; v++) {
            float s = 0.f;
#pragma unroll
            for (int w = 0; w < 8; w++) s += sred[v][w];
            l[v] = s;
        }
        float m = l[0];
#pragma unroll
        for (int e = 1; e < EE; e++) m = fmaxf(m, l[e]);
        float p[EE];
#pragma unroll
        for (int e = 0; e < EE; e++) p[e] = expf(l[e] - m);
        int i0 = 0;
#pragma unroll
        for (int e = 1; e < EE; e++) if (p[e] > p[i0]) i0 = e;
        int i1 = (i0 == 0) ? 1 : 0;
#pragma unroll
        for (int e = 0; e < EE; e++) if (e != i0 && p[e] > p[i1]) i1 = e;
        float inv = 1.f / (p[i0] + p[i1]);
        int q0 = atomicAdd(&g_cnt[i0], 1);
        g_perm[i0 * TT + q0] = t;
        g_cw[i0 * TT + q0]   = p[i0] * inv;
        int q1 = atomicAdd(&g_cnt[i1], 1);
        g_perm[i1 * TT + q1] = t;
        g_cw[i1 * TT + q1]   = p[i1] * inv;
        g_sgate[t] = 1.f / (1.f + expf(-l[8]));
    }
}

// ===================== gate/up GEMM core ==========================================
// block: 128 rows x (64 gate cols + 64 up cols), BK=16, 256 thr, 8x8 thread tile
__device__ __forceinline__ void gateup_core(
    const float* arow0, const float* arow1,   // this thread's 2 A-row pointers
    const float* wg, const float* wu, int Ndim, int colg0, int Kdim,
    float cg[8][4], float cu[8][4])
{
    __shared__ alignas(16) float As[BK][SSTR];   // [k][m] transposed
    __shared__ alignas(16) float Bs[BK][SSTR];   // [k][0:64)=gate, [64:128)=up

    int tid = threadIdx.x;
    int tx = tid & 15, ty = tid >> 4;
    int bk_ = tid >> 4;
    int bn4 = (tid & 15) << 2;
    int ar  = tid >> 2;          // A loader row (i=0: 0..63, i=1: +64)
    int akc = (tid & 3) << 2;    // A loader k quad

    for (int k0 = 0; k0 < Kdim; k0 += BK) {
        // A tile: 128 rows x 16 k, transposed store
        {
            float4 v0 = *(const float4*)(arow0 + k0 + akc);
            float4 v1 = *(const float4*)(arow1 + k0 + akc);
            As[akc + 0][ar] = v0.x; As[akc + 1][ar] = v0.y;
            As[akc + 2][ar] = v0.z; As[akc + 3][ar] = v0.w;
            As[akc + 0][ar + 64] = v1.x; As[akc + 1][ar + 64] = v1.y;
            As[akc + 2][ar + 64] = v1.z; As[akc + 3][ar + 64] = v1.w;
        }
        // B tiles: 16 k x 64 n each of gate/up
        {
            size_t goff = (size_t)(k0 + bk_) * Ndim + colg0 + bn4;
            *(float4*)&Bs[bk_][bn4]      = *(const float4*)(wg + goff);
            *(float4*)&Bs[bk_][bn4 + 64] = *(const float4*)(wu + goff);
        }
        __syncthreads();
#pragma unroll
        for (int kk = 0; kk < BK; kk++) {
            float4 a0 = *(const float4*)&As[kk][ty * 4];
            float4 a1 = *(const float4*)&As[kk][ty * 4 + 64];
            float4 bg = *(const float4*)&Bs[kk][tx * 4];
            float4 bu = *(const float4*)&Bs[kk][tx * 4 + 64];
            float av[8] = { a0.x, a0.y, a0.z, a0.w, a1.x, a1.y, a1.z, a1.w };
            float bgv[4] = { bg.x, bg.y, bg.z, bg.w };
            float buv[4] = { bu.x, bu.y, bu.z, bu.w };
#pragma unroll
            for (int i = 0; i < 8; i++)
#pragma unroll
                for (int j = 0; j < 4; j++) {
                    cg[i][j] = fmaf(av[i], bgv[j], cg[i][j]);
                    cu[i][j] = fmaf(av[i], buv[j], cu[i][j]);
                }
        }
        __syncthreads();
    }
}

// ---------------- expert gate/up --------------------------------------------------
__global__ void __launch_bounds__(256) expert_gateup_kernel(
    const float* __restrict__ x,
    const float* __restrict__ w_gate,
    const float* __restrict__ w_up)
{
    int e = blockIdx.z;
    int nrows = g_cnt[e];
    int row0 = blockIdx.y * 128;
    if (row0 >= nrows) return;
    int colg0 = blockIdx.x * 64;
    const float* wg = w_gate + (size_t)e * DD * HH;
    const float* wu = w_up   + (size_t)e * DD * HH;

    int tid = threadIdx.x;
    int tx = tid & 15, ty = tid >> 4;
    int ar = tid >> 2;

    int pos0 = row0 + ar;
    int pos1 = row0 + ar + 64;
    int tok0 = (pos0 < nrows) ? g_perm[e * TT + pos0] : g_perm[e * TT];
    int tok1 = (pos1 < nrows) ? g_perm[e * TT + pos1] : g_perm[e * TT];

    float cg[8][4], cu[8][4];
#pragma unroll
    for (int i = 0; i < 8; i++)
#pragma unroll
        for (int j = 0; j < 4; j++) { cg[i][j] = 0.f; cu[i][j] = 0.f; }

    gateup_core(x + (size_t)tok0 * DD, x + (size_t)tok1 * DD,
                wg, wu, HH, colg0, DD, cg, cu);

#pragma unroll
    for (int i = 0; i < 8; i++) {
        int pos = row0 + (i < 4 ? ty * 4 + i : 64 + ty * 4 + (i - 4));
        if (pos < nrows) {
            float* o = g_h + ((size_t)e * TT + pos) * HH + colg0 + tx * 4;
            float4 v;
            v.x = cu[i][0] * silu(cg[i][0]);
            v.y = cu[i][1] * silu(cg[i][1]);
            v.z = cu[i][2] * silu(cg[i][2]);
            v.w = cu[i][3] * silu(cg[i][3]);
            *(float4*)o = v;
        }
    }
}

// ---------------- shared gate/up --------------------------------------------------
__global__ void __launch_bounds__(256) shared_gateup_kernel(
    const float* __restrict__ x,
    const float* __restrict__ shw_gate,
    const float* __restrict__ shw_up)
{
    int row0 = blockIdx.y * 128;
    int colg0 = blockIdx.x * 64;

    int tid = threadIdx.x;
    int tx = tid & 15, ty = tid >> 4;
    int ar = tid >> 2;

    float cg[8][4], cu[8][4];
#pragma unroll
    for (int i = 0; i < 8; i++)
#pragma unroll
        for (int j = 0; j < 4; j++) { cg[i][j] = 0.f; cu[i][j] = 0.f; }

    gateup_core(x + (size_t)(row0 + ar) * DD, x + (size_t)(row0 + ar + 64) * DD,
                shw_gate, shw_up, HSD, colg0, DD, cg, cu);

#pragma unroll
    for (int i = 0; i < 8; i++) {
        int pos = row0 + (i < 4 ? ty * 4 + i : 64 + ty * 4 + (i - 4));
        float* o = g_hs + (size_t)pos * HSD + colg0 + tx * 4;
        float4 v;
        v.x = cu[i][0] * silu(cg[i][0]);
        v.y = cu[i][1] * silu(cg[i][1]);
        v.z = cu[i][2] * silu(cg[i][2]);
        v.w = cu[i][3] * silu(cg[i][3]);
        *(float4*)o = v;
    }
}

// ===================== down GEMM core =============================================
// block: 128 rows x 128 cols, BK=16, 256 thr, 8x8 thread tile
__device__ __forceinline__ void down_core(
    const float* arow0, const float* arow1,
    const float* wd, int col0, int Kdim,
    float c[8][8])
{
    __shared__ alignas(16) float As[BK][SSTR];
    __shared__ alignas(16) float Bs[BK][SSTR];

    int tid = threadIdx.x;
    int tx = tid & 15, ty = tid >> 4;
    int ar  = tid >> 2;
    int akc = (tid & 3) << 2;

    for (int k0 = 0; k0 < Kdim; k0 += BK) {
        {
            float4 v0 = *(const float4*)(arow0 + k0 + akc);
            float4 v1 = *(const float4*)(arow1 + k0 + akc);
            As[akc + 0][ar] = v0.x; As[akc + 1][ar] = v0.y;
            As[akc + 2][ar] = v0.z; As[akc + 3][ar] = v0.w;
            As[akc + 0][ar + 64] = v1.x; As[akc + 1][ar + 64] = v1.y;
            As[akc + 2][ar + 64] = v1.z; As[akc + 3][ar + 64] = v1.w;
        }
        // B tile: 16 k x 128 n
#pragma unroll
        for (int i = 0; i < 2; i++) {
            int idx = tid + i * 256;
            int k = idx >> 5;
            int n4 = (idx & 31) << 2;
            *(float4*)&Bs[k][n4] = *(const float4*)(wd + (size_t)(k0 + k) * DD + col0 + n4);
        }
        __syncthreads();
#pragma unroll
        for (int kk = 0; kk < BK; kk++) {
            float4 a0 = *(const float4*)&As[kk][ty * 4];
            float4 a1 = *(const float4*)&As[kk][ty * 4 + 64];
            float4 b0 = *(const float4*)&Bs[kk][tx * 4];
            float4 b1 = *(const float4*)&Bs[kk][tx * 4 + 64];
            float av[8] = { a0.x, a0.y, a0.z, a0.w, a1.x, a1.y, a1.z, a1.w };
            float bv[8] = { b0.x, b0.y, b0.z, b0.w, b1.x, b1.y, b1.z, b1.w };
#pragma unroll
            for (int i = 0; i < 8; i++)
#pragma unroll
                for (int j = 0; j < 8; j++)
                    c[i][j] = fmaf(av[i], bv[j], c[i][j]);
        }
        __syncthreads();
    }
}

// ---------------- shared down ------------------------------------------------------
__global__ void __launch_bounds__(256) shared_down_kernel(
    const float* __restrict__ shw_down,
    float* __restrict__ out)
{
    int row0 = blockIdx.y * 128;
    int col0 = blockIdx.x * 128;

    int tid = threadIdx.x;
    int tx = tid & 15, ty = tid >> 4;
    int ar = tid >> 2;

    float c[8][8];
#pragma unroll
    for (int i = 0; i < 8; i++)
#pragma unroll
        for (int j = 0; j < 8; j++) c[i][j] = 0.f;

    down_core(g_hs + (size_t)(row0 + ar) * HSD, g_hs + (size_t)(row0 + ar + 64) * HSD,
              shw_down, col0, HSD, c);

#pragma unroll
    for (int i = 0; i < 8; i++) {
        int pos = row0 + (i < 4 ? ty * 4 + i : 64 + ty * 4 + (i - 4));
        float sg = g_sgate[pos];
        float* op = out + (size_t)pos * DD + col0;
        float4 v0, v1;
        v0.x = sg * c[i][0]; v0.y = sg * c[i][1]; v0.z = sg * c[i][2]; v0.w = sg * c[i][3];
        v1.x = sg * c[i][4]; v1.y = sg * c[i][5]; v1.z = sg * c[i][6]; v1.w = sg * c[i][7];
        *(float4*)(op + tx * 4) = v0;
        *(float4*)(op + 64 + tx * 4) = v1;
    }
}

// ---------------- expert down -------------------------------------------------------
__global__ void __launch_bounds__(256) expert_down_kernel(
    const float* __restrict__ w_down,
    float* __restrict__ out)
{
    int e = blockIdx.z;
    int nrows = g_cnt[e];
    int row0 = blockIdx.y * 128;
    if (row0 >= nrows) return;
    int col0 = blockIdx.x * 128;
    const float* wd = w_down + (size_t)e * HH * DD;

    int tid = threadIdx.x;
    int tx = tid & 15, ty = tid >> 4;
    int ar = tid >> 2;

    float c[8][8];
#pragma unroll
    for (int i = 0; i < 8; i++)
#pragma unroll
        for (int j = 0; j < 8; j++) c[i][j] = 0.f;

    down_core(g_h + ((size_t)e * TT + row0 + ar) * HH,
              g_h + ((size_t)e * TT + row0 + ar + 64) * HH,
              wd, col0, HH, c);

#pragma unroll
    for (int i = 0; i < 8; i++) {
        int pos = row0 + (i < 4 ? ty * 4 + i : 64 + ty * 4 + (i - 4));
        if (pos < nrows) {
            int tok = g_perm[e * TT + pos];
            float cw = g_cw[e * TT + pos];
            float* op = out + (size_t)tok * DD + col0;
#pragma unroll
            for (int j = 0; j < 4; j++) {
                atomicAdd(op + tx * 4 + j,      cw * c[i][j]);
                atomicAdd(op + 64 + tx * 4 + j, cw * c[i][j + 4]);
            }
        }
    }
}

// ---------------- launch ----------------------------------------------------------
extern "C" void kernel_launch(void* const* d_in, const int* in_sizes, int n_in,
                              void* d_out, int out_size)
{
    const float* x        = (const float*)d_in[0];
    const float* gate_w   = (const float*)d_in[1];
    const float* w_gate   = (const float*)d_in[2];
    const float* w_up     = (const float*)d_in[3];
    const float* w_down   = (const float*)d_in[4];
    const float* shgate_w = (const float*)d_in[5];
    const float* shw_gate = (const float*)d_in[6];
    const float* shw_up   = (const float*)d_in[7];
    const float* shw_down = (const float*)d_in[8];
    float* out = (float*)d_out;

    zero_cnt_kernel<<<1, 32>>>();
    router_kernel<<<TT, 256>>>(x, gate_w, shgate_w);
    expert_gateup_kernel<<<dim3(HH / 64, TT / 128, EE), 256>>>(x, w_gate, w_up);
    shared_gateup_kernel<<<dim3(HSD / 64, TT / 128), 256>>>(x, shw_gate, shw_up);
    shared_down_kernel<<<dim3(DD / 128, TT / 128), 256>>>(shw_down, out);
    expert_down_kernel<<<dim3(DD / 128, TT / 128, EE), 256>>>(w_down, out);
}

// round 12
// speedup vs baseline: 1.3607x; 1.0310x over previous
#include <cuda_runtime.h>
#include <cstdint>

#define TT 2048
#define DD 2048
#define EE 8
#define HH 1408
#define HSD 2816

#define BK 16
#define SSTR 132   // smem row stride (floats) for [BK][128] tiles

__device__ __forceinline__ float silu(float g) { return g / (1.f + __expf(-g)); }

// ---------------- scratch ------------------------------------------------------
__device__ int   g_cnt[EE];
__device__ int   g_perm[EE * TT];
__device__ float g_cw[EE * TT];
__device__ float g_sgate[TT];
__device__ float g_h[(size_t)EE * TT * HH];
__device__ float g_hs[(size_t)TT * HSD];

// ---------------- kernel 0 -------------------------------------------------------
__global__ void zero_cnt_kernel() {
    if (threadIdx.x < EE) g_cnt[threadIdx.x] = 0;
}

// ---------------- kernel 1: router -----------------------------------------------
__global__ void __launch_bounds__(256) router_kernel(
    const float* __restrict__ x,
    const float* __restrict__ gate_w,
    const float* __restrict__ shgate_w)
{
    int t = blockIdx.x;
    const float* xr = x + (size_t)t * DD;
    float acc[9];
#pragma unroll
    for (int v = 0; v < 9; v++) acc[v] = 0.f;
    for (int j = threadIdx.x; j < DD; j += 256) {
        float xv = xr[j];
#pragma unroll
        for (int e = 0; e < EE; e++) acc[e] = fmaf(xv, gate_w[e * DD + j], acc[e]);
        acc[8] = fmaf(xv, shgate_w[j], acc[8]);
    }
#pragma unroll
    for (int o = 16; o > 0; o >>= 1) {
#pragma unroll
        for (int v = 0; v < 9; v++) acc[v] += __shfl_down_sync(0xffffffffu, acc[v], o);
    }
    __shared__ float sred[9][8];
    int lane = threadIdx.x & 31, wid = threadIdx.x >> 5;
    if (lane == 0) {
#pragma unroll
        for (int v = 0; v < 9; v++) sred[v][wid] = acc[v];
    }
    __syncthreads();
    if (threadIdx.x == 0) {
        float l[9];
#pragma unroll
        for (int v = 0; v < 9; v++) {
            float s = 0.f;
#pragma unroll
            for (int w = 0; w < 8; w++) s += sred[v][w];
            l[v] = s;
        }
        float m = l[0];
#pragma unroll
        for (int e = 1; e < EE; e++) m = fmaxf(m, l[e]);
        float p[EE];
#pragma unroll
        for (int e = 0; e < EE; e++) p[e] = expf(l[e] - m);
        int i0 = 0;
#pragma unroll
        for (int e = 1; e < EE; e++) if (p[e] > p[i0]) i0 = e;
        int i1 = (i0 == 0) ? 1 : 0;
#pragma unroll
        for (int e = 0; e < EE; e++) if (e != i0 && p[e] > p[i1]) i1 = e;
        float inv = 1.f / (p[i0] + p[i1]);
        int q0 = atomicAdd(&g_cnt[i0], 1);
        g_perm[i0 * TT + q0] = t;
        g_cw[i0 * TT + q0]   = p[i0] * inv;
        int q1 = atomicAdd(&g_cnt[i1], 1);
        g_perm[i1 * TT + q1] = t;
        g_cw[i1 * TT + q1]   = p[i1] * inv;
        g_sgate[t] = 1.f / (1.f + expf(-l[8]));
    }
}

// ===================== gate/up GEMM core (double-buffered) =========================
// block: 128 rows x (64 gate + 64 up cols), BK=16, 256 thr, 8x8 thread tile
__device__ __forceinline__ void gateup_core(
    const float* arow0, const float* arow1,
    const float* wg, const float* wu, int Ndim, int colg0, int Kdim,
    float cg[8][4], float cu[8][4])
{
    __shared__ alignas(16) float As[2][BK][SSTR];
    __shared__ alignas(16) float Bs[2][BK][SSTR];

    int tid = threadIdx.x;
    int tx = tid & 15, ty = tid >> 4;
    int bk_ = tid >> 4;
    int bn4 = (tid & 15) << 2;
    int ar  = tid >> 2;
    int akc = (tid & 3) << 2;

    const int NS = Kdim / BK;

    // preload slab 0 into buffer 0
    {
        float4 v0 = *(const float4*)(arow0 + akc);
        float4 v1 = *(const float4*)(arow1 + akc);
        As[0][akc + 0][ar] = v0.x; As[0][akc + 1][ar] = v0.y;
        As[0][akc + 2][ar] = v0.z; As[0][akc + 3][ar] = v0.w;
        As[0][akc + 0][ar + 64] = v1.x; As[0][akc + 1][ar + 64] = v1.y;
        As[0][akc + 2][ar + 64] = v1.z; As[0][akc + 3][ar + 64] = v1.w;
        size_t goff = (size_t)bk_ * Ndim + colg0 + bn4;
        *(float4*)&Bs[0][bk_][bn4]      = *(const float4*)(wg + goff);
        *(float4*)&Bs[0][bk_][bn4 + 64] = *(const float4*)(wu + goff);
    }
    __syncthreads();

    for (int s = 0; s < NS; s++) {
        int cur = s & 1;
        float4 pa0, pa1, pbg, pbu;
        if (s + 1 < NS) {
            int k1 = (s + 1) * BK;
            pa0 = *(const float4*)(arow0 + k1 + akc);
            pa1 = *(const float4*)(arow1 + k1 + akc);
            size_t goff = (size_t)(k1 + bk_) * Ndim + colg0 + bn4;
            pbg = *(const float4*)(wg + goff);
            pbu = *(const float4*)(wu + goff);
        }
        const float (*Ac)[SSTR] = As[cur];
        const float (*Bc)[SSTR] = Bs[cur];
#pragma unroll
        for (int kk = 0; kk < BK; kk++) {
            float4 a0 = *(const float4*)&Ac[kk][ty * 4];
            float4 a1 = *(const float4*)&Ac[kk][ty * 4 + 64];
            float4 bg = *(const float4*)&Bc[kk][tx * 4];
            float4 bu = *(const float4*)&Bc[kk][tx * 4 + 64];
            float av[8] = { a0.x, a0.y, a0.z, a0.w, a1.x, a1.y, a1.z, a1.w };
            float bgv[4] = { bg.x, bg.y, bg.z, bg.w };
            float buv[4] = { bu.x, bu.y, bu.z, bu.w };
#pragma unroll
            for (int i = 0; i < 8; i++)
#pragma unroll
                for (int j = 0; j < 4; j++) {
                    cg[i][j] = fmaf(av[i], bgv[j], cg[i][j]);
                    cu[i][j] = fmaf(av[i], buv[j], cu[i][j]);
                }
        }
        if (s + 1 < NS) {
            int nxt = cur ^ 1;
            As[nxt][akc + 0][ar] = pa0.x; As[nxt][akc + 1][ar] = pa0.y;
            As[nxt][akc + 2][ar] = pa0.z; As[nxt][akc + 3][ar] = pa0.w;
            As[nxt][akc + 0][ar + 64] = pa1.x; As[nxt][akc + 1][ar + 64] = pa1.y;
            As[nxt][akc + 2][ar + 64] = pa1.z; As[nxt][akc + 3][ar + 64] = pa1.w;
            *(float4*)&Bs[nxt][bk_][bn4]      = pbg;
            *(float4*)&Bs[nxt][bk_][bn4 + 64] = pbu;
            __syncthreads();
        }
    }
}

// ---------------- expert gate/up --------------------------------------------------
__global__ void __launch_bounds__(256, 2) expert_gateup_kernel(
    const float* __restrict__ x,
    const float* __restrict__ w_gate,
    const float* __restrict__ w_up)
{
    int e = blockIdx.z;
    int nrows = g_cnt[e];
    int row0 = blockIdx.y * 128;
    if (row0 >= nrows) return;
    int colg0 = blockIdx.x * 64;
    const float* wg = w_gate + (size_t)e * DD * HH;
    const float* wu = w_up   + (size_t)e * DD * HH;

    int tid = threadIdx.x;
    int tx = tid & 15, ty = tid >> 4;
    int ar = tid >> 2;

    int pos0 = row0 + ar;
    int pos1 = row0 + ar + 64;
    int tok0 = (pos0 < nrows) ? g_perm[e * TT + pos0] : g_perm[e * TT];
    int tok1 = (pos1 < nrows) ? g_perm[e * TT + pos1] : g_perm[e * TT];

    float cg[8][4], cu[8][4];
#pragma unroll
    for (int i = 0; i < 8; i++)
#pragma unroll
        for (int j = 0; j < 4; j++) { cg[i][j] = 0.f; cu[i][j] = 0.f; }

    gateup_core(x + (size_t)tok0 * DD, x + (size_t)tok1 * DD,
                wg, wu, HH, colg0, DD, cg, cu);

#pragma unroll
    for (int i = 0; i < 8; i++) {
        int pos = row0 + (i < 4 ? ty * 4 + i : 64 + ty * 4 + (i - 4));
        if (pos < nrows) {
            float* o = g_h + ((size_t)e * TT + pos) * HH + colg0 + tx * 4;
            float4 v;
            v.x = cu[i][0] * silu(cg[i][0]);
            v.y = cu[i][1] * silu(cg[i][1]);
            v.z = cu[i][2] * silu(cg[i][2]);
            v.w = cu[i][3] * silu(cg[i][3]);
            *(float4*)o = v;
        }
    }
}

// ---------------- shared gate/up --------------------------------------------------
__global__ void __launch_bounds__(256, 2) shared_gateup_kernel(
    const float* __restrict__ x,
    const float* __restrict__ shw_gate,
    const float* __restrict__ shw_up)
{
    int row0 = blockIdx.y * 128;
    int colg0 = blockIdx.x * 64;

    int tid = threadIdx.x;
    int tx = tid & 15, ty = tid >> 4;
    int ar = tid >> 2;

    float cg[8][4], cu[8][4];
#pragma unroll
    for (int i = 0; i < 8; i++)
#pragma unroll
        for (int j = 0; j < 4; j++) { cg[i][j] = 0.f; cu[i][j] = 0.f; }

    gateup_core(x + (size_t)(row0 + ar) * DD, x + (size_t)(row0 + ar + 64) * DD,
                shw_gate, shw_up, HSD, colg0, DD, cg, cu);

#pragma unroll
    for (int i = 0; i < 8; i++) {
        int pos = row0 + (i < 4 ? ty * 4 + i : 64 + ty * 4 + (i - 4));
        float* o = g_hs + (size_t)pos * HSD + colg0 + tx * 4;
        float4 v;
        v.x = cu[i][0] * silu(cg[i][0]);
        v.y = cu[i][1] * silu(cg[i][1]);
        v.z = cu[i][2] * silu(cg[i][2]);
        v.w = cu[i][3] * silu(cg[i][3]);
        *(float4*)o = v;
    }
}

// ===================== down GEMM core (double-buffered) ============================
// block: 128 rows x 128 cols, BK=16, 256 thr, 8x8 thread tile
__device__ __forceinline__ void down_core(
    const float* arow0, const float* arow1,
    const float* wd, int col0, int Kdim,
    float c[8][8])
{
    __shared__ alignas(16) float As[2][BK][SSTR];
    __shared__ alignas(16) float Bs[2][BK][SSTR];

    int tid = threadIdx.x;
    int tx = tid & 15, ty = tid >> 4;
    int ar  = tid >> 2;
    int akc = (tid & 3) << 2;
    int bk0 = tid >> 5;            // B loader: rows tid/32 and tid/32+8
    int bn4 = (tid & 31) << 2;

    const int NS = Kdim / BK;

    {
        float4 v0 = *(const float4*)(arow0 + akc);
        float4 v1 = *(const float4*)(arow1 + akc);
        As[0][akc + 0][ar] = v0.x; As[0][akc + 1][ar] = v0.y;
        As[0][akc + 2][ar] = v0.z; As[0][akc + 3][ar] = v0.w;
        As[0][akc + 0][ar + 64] = v1.x; As[0][akc + 1][ar + 64] = v1.y;
        As[0][akc + 2][ar + 64] = v1.z; As[0][akc + 3][ar + 64] = v1.w;
        *(float4*)&Bs[0][bk0][bn4]     = *(const float4*)(wd + (size_t)bk0 * DD + col0 + bn4);
        *(float4*)&Bs[0][bk0 + 8][bn4] = *(const float4*)(wd + (size_t)(bk0 + 8) * DD + col0 + bn4);
    }
    __syncthreads();

    for (int s = 0; s < NS; s++) {
        int cur = s & 1;
        float4 pa0, pa1, pb0, pb1;
        if (s + 1 < NS) {
            int k1 = (s + 1) * BK;
            pa0 = *(const float4*)(arow0 + k1 + akc);
            pa1 = *(const float4*)(arow1 + k1 + akc);
            pb0 = *(const float4*)(wd + (size_t)(k1 + bk0) * DD + col0 + bn4);
            pb1 = *(const float4*)(wd + (size_t)(k1 + bk0 + 8) * DD + col0 + bn4);
        }
        const float (*Ac)[SSTR] = As[cur];
        const float (*Bc)[SSTR] = Bs[cur];
#pragma unroll
        for (int kk = 0; kk < BK; kk++) {
            float4 a0 = *(const float4*)&Ac[kk][ty * 4];
            float4 a1 = *(const float4*)&Ac[kk][ty * 4 + 64];
            float4 b0 = *(const float4*)&Bc[kk][tx * 4];
            float4 b1 = *(const float4*)&Bc[kk][tx * 4 + 64];
            float av[8] = { a0.x, a0.y, a0.z, a0.w, a1.x, a1.y, a1.z, a1.w };
            float bv[8] = { b0.x, b0.y, b0.z, b0.w, b1.x, b1.y, b1.z, b1.w };
#pragma unroll
            for (int i = 0; i < 8; i++)
#pragma unroll
                for (int j = 0; j < 8; j++)
                    c[i][j] = fmaf(av[i], bv[j], c[i][j]);
        }
        if (s + 1 < NS) {
            int nxt = cur ^ 1;
            As[nxt][akc + 0][ar] = pa0.x; As[nxt][akc + 1][ar] = pa0.y;
            As[nxt][akc + 2][ar] = pa0.z; As[nxt][akc + 3][ar] = pa0.w;
            As[nxt][akc + 0][ar + 64] = pa1.x; As[nxt][akc + 1][ar + 64] = pa1.y;
            As[nxt][akc + 2][ar + 64] = pa1.z; As[nxt][akc + 3][ar + 64] = pa1.w;
            *(float4*)&Bs[nxt][bk0][bn4]     = pb0;
            *(float4*)&Bs[nxt][bk0 + 8][bn4] = pb1;
            __syncthreads();
        }
    }
}

// ---------------- shared down ------------------------------------------------------
__global__ void __launch_bounds__(256, 2) shared_down_kernel(
    const float* __restrict__ shw_down,
    float* __restrict__ out)
{
    int row0 = blockIdx.y * 128;
    int col0 = blockIdx.x * 128;

    int tid = threadIdx.x;
    int tx = tid & 15, ty = tid >> 4;
    int ar = tid >> 2;

    float c[8][8];
#pragma unroll
    for (int i = 0; i < 8; i++)
#pragma unroll
        for (int j = 0; j < 8; j++) c[i][j] = 0.f;

    down_core(g_hs + (size_t)(row0 + ar) * HSD, g_hs + (size_t)(row0 + ar + 64) * HSD,
              shw_down, col0, HSD, c);

#pragma unroll
    for (int i = 0; i < 8; i++) {
        int pos = row0 + (i < 4 ? ty * 4 + i : 64 + ty * 4 + (i - 4));
        float sg = g_sgate[pos];
        float* op = out + (size_t)pos * DD + col0;
        float4 v0, v1;
        v0.x = sg * c[i][0]; v0.y = sg * c[i][1]; v0.z = sg * c[i][2]; v0.w = sg * c[i][3];
        v1.x = sg * c[i][4]; v1.y = sg * c[i][5]; v1.z = sg * c[i][6]; v1.w = sg * c[i][7];
        *(float4*)(op + tx * 4) = v0;
        *(float4*)(op + 64 + tx * 4) = v1;
    }
}

// ---------------- expert down -------------------------------------------------------
__global__ void __launch_bounds__(256, 2) expert_down_kernel(
    const float* __restrict__ w_down,
    float* __restrict__ out)
{
    int e = blockIdx.z;
    int nrows = g_cnt[e];
    int row0 = blockIdx.y * 128;
    if (row0 >= nrows) return;
    int col0 = blockIdx.x * 128;
    const float* wd = w_down + (size_t)e * HH * DD;

    int tid = threadIdx.x;
    int tx = tid & 15, ty = tid >> 4;
    int ar = tid >> 2;

    float c[8][8];
#pragma unroll
    for (int i = 0; i < 8; i++)
#pragma unroll
        for (int j = 0; j < 8; j++) c[i][j] = 0.f;

    down_core(g_h + ((size_t)e * TT + row0 + ar) * HH,
              g_h + ((size_t)e * TT + row0 + ar + 64) * HH,
              wd, col0, HH, c);

#pragma unroll
    for (int i = 0; i < 8; i++) {
        int pos = row0 + (i < 4 ? ty * 4 + i : 64 + ty * 4 + (i - 4));
        if (pos < nrows) {
            int tok = g_perm[e * TT + pos];
            float cw = g_cw[e * TT + pos];
            float* op = out + (size_t)tok * DD + col0;
#pragma unroll
            for (int j = 0; j < 4; j++) {
                atomicAdd(op + tx * 4 + j,      cw * c[i][j]);
                atomicAdd(op + 64 + tx * 4 + j, cw * c[i][j + 4]);
            }
        }
    }
}

// ---------------- launch ----------------------------------------------------------
extern "C" void kernel_launch(void* const* d_in, const int* in_sizes, int n_in,
                              void* d_out, int out_size)
{
    const float* x        = (const float*)d_in[0];
    const float* gate_w   = (const float*)d_in[1];
    const float* w_gate   = (const float*)d_in[2];
    const float* w_up     = (const float*)d_in[3];
    const float* w_down   = (const float*)d_in[4];
    const float* shgate_w = (const float*)d_in[5];
    const float* shw_gate = (const float*)d_in[6];
    const float* shw_up   = (const float*)d_in[7];
    const float* shw_down = (const float*)d_in[8];
    float* out = (float*)d_out;

    zero_cnt_kernel<<<1, 32>>>();
    router_kernel<<<TT, 256>>>(x, gate_w, shgate_w);
    expert_gateup_kernel<<<dim3(HH / 64, TT / 128, EE), 256>>>(x, w_gate, w_up);
    shared_gateup_kernel<<<dim3(HSD / 64, TT / 128), 256>>>(x, shw_gate, shw_up);
    shared_down_kernel<<<dim3(DD / 128, TT / 128), 256>>>(shw_down, out);
    expert_down_kernel<<<dim3(DD / 128, TT / 128, EE), 256>>>(w_down, out);
}